// round 1
// baseline (speedup 1.0000x reference)
#include <cuda_runtime.h>
#include <cuda_bf16.h>
#include <cstdint>

#define V_SIZE 50257
#define NP     50304          // 393 * 128 (padded vocab)
#define KDIM   768
#define MROWS  2048
#define HD     769
#define LOG_V  10.8249046870f
#define LOG2E  1.44269504089f

// -------- scratch (device globals; no allocation allowed) --------
__device__ __align__(16) __nv_bfloat16 g_Wn[(size_t)NP * KDIM];   // ~77 MB
__device__ __align__(16) __nv_bfloat16 g_Un[(size_t)MROWS * KDIM];
__device__ float g_rs[MROWS];
__device__ float g_S1[MROWS];
__device__ float g_S2[MROWS];
__device__ float g_S3[MROWS];

// ---------------- prep: normalize W_vocab rows -> bf16 ----------------
__global__ __launch_bounds__(128) void prep_w_kernel(const float* __restrict__ W) {
    int v = blockIdx.x;
    int t = threadIdx.x;
    if (v >= V_SIZE) {
        #pragma unroll
        for (int j = 0; j < 6; ++j)
            g_Wn[(size_t)v * KDIM + t + j * 128] = __float2bfloat16(0.f);
        return;
    }
    const float* row = W + (size_t)v * HD + 1;
    float sp[6]; float ss = 0.f;
    #pragma unroll
    for (int j = 0; j < 6; ++j) { sp[j] = row[t + j * 128]; ss += sp[j] * sp[j]; }
    #pragma unroll
    for (int o = 16; o > 0; o >>= 1) ss += __shfl_xor_sync(0xffffffffu, ss, o);
    __shared__ float sw[4];
    __shared__ float stot;
    if ((t & 31) == 0) sw[t >> 5] = ss;
    __syncthreads();
    if (t == 0) stot = sqrtf(sw[0] + sw[1] + sw[2] + sw[3]);
    __syncthreads();
    float inv = 1.f / fmaxf(stot, 1e-12f);
    #pragma unroll
    for (int j = 0; j < 6; ++j)
        g_Wn[(size_t)v * KDIM + t + j * 128] = __float2bfloat16(sp[j] * inv);
}

// ---------------- prep: normalize h_student rows, r_s, zero accumulators ----------------
__global__ __launch_bounds__(128) void prep_s_kernel(const float* __restrict__ H) {
    int m = blockIdx.x;
    int t = threadIdx.x;
    const float* row = H + (size_t)m * HD + 1;
    float sp[6]; float ss = 0.f;
    #pragma unroll
    for (int j = 0; j < 6; ++j) { sp[j] = row[t + j * 128]; ss += sp[j] * sp[j]; }
    #pragma unroll
    for (int o = 16; o > 0; o >>= 1) ss += __shfl_xor_sync(0xffffffffu, ss, o);
    __shared__ float sw[4];
    __shared__ float stot;
    if ((t & 31) == 0) sw[t >> 5] = ss;
    __syncthreads();
    if (t == 0) {
        stot = sqrtf(sw[0] + sw[1] + sw[2] + sw[3]);
        float x0 = fmaxf(H[(size_t)m * HD], 1.f + 1e-7f);
        g_rs[m] = acoshf(x0);
        g_S1[m] = 0.f; g_S2[m] = 0.f; g_S3[m] = 0.f;
    }
    __syncthreads();
    float inv = 1.f / fmaxf(stot, 1e-12f);
    #pragma unroll
    for (int j = 0; j < 6; ++j)
        g_Un[(size_t)m * KDIM + t + j * 128] = __float2bfloat16(sp[j] * inv);
}

// ---------------- fused GEMM + softmax-KL reductions ----------------
// BM=128, BN=128, BK=32. 256 threads = 8 warps in a 4(M) x 2(N) grid.
// Each warp: 32x64 via m16n8k16 (2 x 8 mma tiles).
__global__ __launch_bounds__(256) void gemm_fused_kernel(const float* __restrict__ P) {
    const int tid  = threadIdx.x;
    const int lane = tid & 31;
    const int warp = tid >> 5;
    const int wm   = warp & 3;   // 0..3 along M
    const int wn   = warp >> 2;  // 0..1 along N
    const int mt   = blockIdx.x; // fast: 16 CTAs share one W tile (L2 reuse of W)
    const int nt   = blockIdx.y;

    __shared__ __align__(16) __nv_bfloat16 As[128 * 40];
    __shared__ __align__(16) __nv_bfloat16 Bs[128 * 40];

    float acc[2][8][4];
    #pragma unroll
    for (int a = 0; a < 2; ++a)
        #pragma unroll
        for (int b = 0; b < 8; ++b)
            #pragma unroll
            for (int c = 0; c < 4; ++c) acc[a][b][c] = 0.f;

    const __nv_bfloat16* GA = g_Un + (size_t)mt * 128 * KDIM;
    const __nv_bfloat16* GB = g_Wn + (size_t)nt * 128 * KDIM;

    const uint32_t asBase = (uint32_t)__cvta_generic_to_shared(As);
    const uint32_t bsBase = (uint32_t)__cvta_generic_to_shared(Bs);

    const int ldr = tid >> 2;            // 0..63 row for gmem->smem
    const int ldc = (tid & 3) * 8;       // 0,8,16,24 (bf16 cols)

    for (int kt = 0; kt < KDIM / 32; ++kt) {
        __syncthreads();
        #pragma unroll
        for (int it = 0; it < 2; ++it) {
            int r = ldr + it * 64;
            *(uint4*)(As + r * 40 + ldc) =
                *(const uint4*)(GA + (size_t)r * KDIM + kt * 32 + ldc);
            *(uint4*)(Bs + r * 40 + ldc) =
                *(const uint4*)(GB + (size_t)r * KDIM + kt * 32 + ldc);
        }
        __syncthreads();

        #pragma unroll
        for (int kk = 0; kk < 2; ++kk) {
            const int kb = kk * 16;
            uint32_t a[2][4];
            #pragma unroll
            for (int mi = 0; mi < 2; ++mi) {
                int row = wm * 32 + mi * 16 + (lane & 15);
                int col = kb + ((lane >> 4) << 3);
                uint32_t addr = asBase + (uint32_t)(row * 40 + col) * 2u;
                asm volatile("ldmatrix.sync.aligned.m8n8.x4.shared.b16 {%0,%1,%2,%3}, [%4];"
                    : "=r"(a[mi][0]), "=r"(a[mi][1]), "=r"(a[mi][2]), "=r"(a[mi][3])
                    : "r"(addr));
            }
            #pragma unroll
            for (int ni = 0; ni < 8; ++ni) {
                int row = wn * 64 + ni * 8 + (lane & 7);
                int col = kb + ((lane >> 3) & 1) * 8;
                uint32_t addr = bsBase + (uint32_t)(row * 40 + col) * 2u;
                uint32_t b0, b1;
                asm volatile("ldmatrix.sync.aligned.m8n8.x2.shared.b16 {%0,%1}, [%2];"
                    : "=r"(b0), "=r"(b1) : "r"(addr));
                #pragma unroll
                for (int mi = 0; mi < 2; ++mi) {
                    asm volatile(
                        "mma.sync.aligned.m16n8k16.row.col.f32.bf16.bf16.f32 "
                        "{%0,%1,%2,%3}, {%4,%5,%6,%7}, {%8,%9}, {%0,%1,%2,%3};"
                        : "+f"(acc[mi][ni][0]), "+f"(acc[mi][ni][1]),
                          "+f"(acc[mi][ni][2]), "+f"(acc[mi][ni][3])
                        : "r"(a[mi][0]), "r"(a[mi][1]), "r"(a[mi][2]), "r"(a[mi][3]),
                          "r"(b0), "r"(b1));
                }
            }
        }
    }

    // ---- epilogue: per-row S1 += exp(logit-1), S2 += p*logit, S3 += p*log(p) ----
    const int rowBase = mt * 128 + wm * 32 + (lane >> 2);
    const int colBase = nt * 128 + wn * 64 + ((lane & 3) << 1);

    #pragma unroll
    for (int mi = 0; mi < 2; ++mi) {
        #pragma unroll
        for (int h = 0; h < 2; ++h) {
            const int r = rowBase + mi * 16 + h * 8;
            const float* Prow = P + (size_t)r * V_SIZE;
            float s1 = 0.f, s2 = 0.f, s3 = 0.f;
            #pragma unroll
            for (int ni = 0; ni < 8; ++ni) {
                #pragma unroll
                for (int e = 0; e < 2; ++e) {
                    int v = colBase + ni * 8 + e;
                    if (v < V_SIZE) {
                        float lg = acc[mi][ni][h * 2 + e];
                        float p  = __ldg(Prow + v);
                        s1 += exp2f(fmaf(lg, LOG2E, -LOG2E));
                        s2 = fmaf(p, lg, s2);
                        s3 = fmaf(p, __logf(fmaxf(p, 1e-12f)), s3);
                    }
                }
            }
            s1 += __shfl_xor_sync(0xffffffffu, s1, 1);
            s1 += __shfl_xor_sync(0xffffffffu, s1, 2);
            s2 += __shfl_xor_sync(0xffffffffu, s2, 1);
            s2 += __shfl_xor_sync(0xffffffffu, s2, 2);
            s3 += __shfl_xor_sync(0xffffffffu, s3, 1);
            s3 += __shfl_xor_sync(0xffffffffu, s3, 2);
            if ((lane & 3) == 0) {
                atomicAdd(&g_S1[r], s1);
                atomicAdd(&g_S2[r], s2);
                atomicAdd(&g_S3[r], s3);
            }
        }
    }
}

// ---------------- finalize: combine per-row stats + radial loss ----------------
__global__ __launch_bounds__(256) void finalize_kernel(const float* __restrict__ TE,
                                                       float* __restrict__ out) {
    const int t = threadIdx.x;
    float kl = 0.f, rs = 0.f, sq = 0.f, rt = 0.f, hn = 0.f;
    for (int r = t; r < MROWS; r += 256) {
        kl += g_S3[r] - g_S2[r] + 1.f + __logf(g_S1[r]);
        float rr = g_rs[r];
        rs += rr;
        float Hn = fminf(fmaxf(TE[r] * (1.f / LOG_V), 0.f), 1.f);
        float rtg = 3.0f / (1.f + expf(Hn));   // sigmoid(-H) * R_MAX
        float d = rr - rtg;
        sq = fmaf(d, d, sq);
        rt += rtg;
        hn += Hn;
    }
    __shared__ float sdata[256];
    float vals[5] = {kl, rs, sq, rt, hn};
    __shared__ float res[5];
    #pragma unroll
    for (int i = 0; i < 5; ++i) {
        __syncthreads();
        sdata[t] = vals[i];
        __syncthreads();
        for (int s = 128; s > 0; s >>= 1) {
            if (t < s) sdata[t] += sdata[t + s];
            __syncthreads();
        }
        if (t == 0) res[i] = sdata[0];
    }
    __syncthreads();
    if (t == 0) {
        const float inv = 1.f / (float)MROWS;
        float l_ang = res[0] * inv;
        float l_rad = res[2] * inv;
        out[0] = l_ang + 0.1f * l_rad;
        out[1] = l_ang;
        out[2] = l_rad;
        out[3] = res[1] * inv;   // mean r_s
        out[4] = res[3] * inv;   // mean r_target
        out[5] = res[4] * inv;   // mean H_norm
    }
}

// ---------------- launch ----------------
extern "C" void kernel_launch(void* const* d_in, const int* in_sizes, int n_in,
                              void* d_out, int out_size) {
    const float* h  = (const float*)d_in[0];   // (2,1024,769)
    const float* W  = (const float*)d_in[1];   // (50257,769)
    const float* P  = (const float*)d_in[2];   // (2,1024,50257)
    const float* TE = (const float*)d_in[3];   // (2,1024)
    float* out = (float*)d_out;

    prep_w_kernel<<<NP, 128>>>(W);
    prep_s_kernel<<<MROWS, 128>>>(h);
    gemm_fused_kernel<<<dim3(MROWS / 128, NP / 128), 256>>>(P);
    finalize_kernel<<<1, 256>>>(TE, out);
}

// round 2
// speedup vs baseline: 1.2011x; 1.2011x over previous
#include <cuda_runtime.h>
#include <cuda_bf16.h>
#include <cstdint>

#define V_SIZE 50257
#define NP     50304          // 393 * 128 (padded vocab)
#define KDIM   768
#define MROWS  2048
#define HD     769
#define LOG_V  10.8249046870f
#define LOG2E  1.44269504089f
#define NKT    24             // KDIM / 32

// -------- scratch (device globals; no allocation allowed) --------
__device__ __align__(16) __nv_bfloat16 g_Wn[(size_t)NP * KDIM];   // ~77 MB
__device__ __align__(16) __nv_bfloat16 g_Un[(size_t)MROWS * KDIM];
__device__ float g_rs[MROWS];
__device__ float g_S1[MROWS];
__device__ float g_S2[MROWS];
__device__ float g_S3[MROWS];

__device__ __forceinline__ void cpa16(uint32_t saddr, const void* gaddr) {
    asm volatile("cp.async.cg.shared.global [%0], [%1], 16;\n"
                 :: "r"(saddr), "l"(gaddr));
}

// ---------------- prep: normalize W_vocab rows -> bf16 ----------------
__global__ __launch_bounds__(128) void prep_w_kernel(const float* __restrict__ W) {
    int v = blockIdx.x;
    int t = threadIdx.x;
    if (v >= V_SIZE) {
        #pragma unroll
        for (int j = 0; j < 6; ++j)
            g_Wn[(size_t)v * KDIM + t + j * 128] = __float2bfloat16(0.f);
        return;
    }
    const float* row = W + (size_t)v * HD + 1;
    float sp[6]; float ss = 0.f;
    #pragma unroll
    for (int j = 0; j < 6; ++j) { sp[j] = row[t + j * 128]; ss += sp[j] * sp[j]; }
    #pragma unroll
    for (int o = 16; o > 0; o >>= 1) ss += __shfl_xor_sync(0xffffffffu, ss, o);
    __shared__ float sw[4];
    __shared__ float stot;
    if ((t & 31) == 0) sw[t >> 5] = ss;
    __syncthreads();
    if (t == 0) stot = sqrtf(sw[0] + sw[1] + sw[2] + sw[3]);
    __syncthreads();
    float inv = 1.f / fmaxf(stot, 1e-12f);
    #pragma unroll
    for (int j = 0; j < 6; ++j)
        g_Wn[(size_t)v * KDIM + t + j * 128] = __float2bfloat16(sp[j] * inv);
}

// ---------------- prep: normalize h_student rows, r_s, zero accumulators ----------------
__global__ __launch_bounds__(128) void prep_s_kernel(const float* __restrict__ H) {
    int m = blockIdx.x;
    int t = threadIdx.x;
    const float* row = H + (size_t)m * HD + 1;
    float sp[6]; float ss = 0.f;
    #pragma unroll
    for (int j = 0; j < 6; ++j) { sp[j] = row[t + j * 128]; ss += sp[j] * sp[j]; }
    #pragma unroll
    for (int o = 16; o > 0; o >>= 1) ss += __shfl_xor_sync(0xffffffffu, ss, o);
    __shared__ float sw[4];
    __shared__ float stot;
    if ((t & 31) == 0) sw[t >> 5] = ss;
    __syncthreads();
    if (t == 0) {
        stot = sqrtf(sw[0] + sw[1] + sw[2] + sw[3]);
        float x0 = fmaxf(H[(size_t)m * HD], 1.f + 1e-7f);
        g_rs[m] = acoshf(x0);
        g_S1[m] = 0.f; g_S2[m] = 0.f; g_S3[m] = 0.f;
    }
    __syncthreads();
    float inv = 1.f / fmaxf(stot, 1e-12f);
    #pragma unroll
    for (int j = 0; j < 6; ++j)
        g_Un[(size_t)m * KDIM + t + j * 128] = __float2bfloat16(sp[j] * inv);
}

// ---------------- fused GEMM + softmax-KL reductions ----------------
// BM=128, BN=128, BK=32, 2-stage cp.async pipeline.
// 256 threads = 8 warps (4 along M x 2 along N); warp tile 32x64 via m16n8k16.
__global__ __launch_bounds__(256, 2) void gemm_fused_kernel(const float* __restrict__ P) {
    const int tid  = threadIdx.x;
    const int lane = tid & 31;
    const int warp = tid >> 5;
    const int wm   = warp & 3;   // 0..3 along M
    const int wn   = warp >> 2;  // 0..1 along N
    const int mt   = blockIdx.x; // fast: 16 CTAs share one W tile (L2 reuse)
    const int nt   = blockIdx.y;

    // 4 buffers of 128x(32+8pad) bf16: A0,A1,B0,B1 = 40KB
    __shared__ __align__(16) __nv_bfloat16 sm[4 * 128 * 40];

    float acc[2][8][4];
    #pragma unroll
    for (int a = 0; a < 2; ++a)
        #pragma unroll
        for (int b = 0; b < 8; ++b)
            #pragma unroll
            for (int c = 0; c < 4; ++c) acc[a][b][c] = 0.f;

    const __nv_bfloat16* GA = g_Un + (size_t)mt * 128 * KDIM;
    const __nv_bfloat16* GB = g_Wn + (size_t)nt * 128 * KDIM;
    const uint32_t smBase = (uint32_t)__cvta_generic_to_shared(sm);

    const int ldrow = tid >> 2;        // 0..63
    const int ldcol = (tid & 3) * 8;   // 0,8,16,24 (bf16)

    auto load_stage = [&](int kt, int buf) {
        #pragma unroll
        for (int it = 0; it < 2; ++it) {
            const int r = ldrow + it * 64;
            cpa16(smBase + (uint32_t)((buf * 5120) + r * 40 + ldcol) * 2u,
                  GA + (size_t)r * KDIM + kt * 32 + ldcol);
            cpa16(smBase + (uint32_t)(((2 + buf) * 5120) + r * 40 + ldcol) * 2u,
                  GB + (size_t)r * KDIM + kt * 32 + ldcol);
        }
        asm volatile("cp.async.commit_group;\n" ::: "memory");
    };

    load_stage(0, 0);
    load_stage(1, 1);

    for (int kt = 0; kt < NKT; ++kt) {
        asm volatile("cp.async.wait_group 1;\n" ::: "memory");
        __syncthreads();

        const int buf = kt & 1;
        const uint32_t aBase = smBase + (uint32_t)(buf * 5120) * 2u;
        const uint32_t bBase = smBase + (uint32_t)((2 + buf) * 5120) * 2u;

        #pragma unroll
        for (int kk = 0; kk < 2; ++kk) {
            const int kb = kk * 16;
            uint32_t a[2][4];
            #pragma unroll
            for (int mi = 0; mi < 2; ++mi) {
                int row = wm * 32 + mi * 16 + (lane & 15);
                int col = kb + ((lane >> 4) << 3);
                uint32_t addr = aBase + (uint32_t)(row * 40 + col) * 2u;
                asm volatile("ldmatrix.sync.aligned.m8n8.x4.shared.b16 {%0,%1,%2,%3}, [%4];"
                    : "=r"(a[mi][0]), "=r"(a[mi][1]), "=r"(a[mi][2]), "=r"(a[mi][3])
                    : "r"(addr));
            }
            #pragma unroll
            for (int np = 0; np < 4; ++np) {
                // two n-tiles (2np, 2np+1) per ldmatrix.x4
                int row = wn * 64 + np * 16 + ((lane >> 4) & 1) * 8 + (lane & 7);
                int col = kb + ((lane >> 3) & 1) * 8;
                uint32_t addr = bBase + (uint32_t)(row * 40 + col) * 2u;
                uint32_t b0, b1, b2, b3;
                asm volatile("ldmatrix.sync.aligned.m8n8.x4.shared.b16 {%0,%1,%2,%3}, [%4];"
                    : "=r"(b0), "=r"(b1), "=r"(b2), "=r"(b3) : "r"(addr));
                #pragma unroll
                for (int mi = 0; mi < 2; ++mi) {
                    asm volatile(
                        "mma.sync.aligned.m16n8k16.row.col.f32.bf16.bf16.f32 "
                        "{%0,%1,%2,%3}, {%4,%5,%6,%7}, {%8,%9}, {%0,%1,%2,%3};"
                        : "+f"(acc[mi][2 * np][0]), "+f"(acc[mi][2 * np][1]),
                          "+f"(acc[mi][2 * np][2]), "+f"(acc[mi][2 * np][3])
                        : "r"(a[mi][0]), "r"(a[mi][1]), "r"(a[mi][2]), "r"(a[mi][3]),
                          "r"(b0), "r"(b1));
                    asm volatile(
                        "mma.sync.aligned.m16n8k16.row.col.f32.bf16.bf16.f32 "
                        "{%0,%1,%2,%3}, {%4,%5,%6,%7}, {%8,%9}, {%0,%1,%2,%3};"
                        : "+f"(acc[mi][2 * np + 1][0]), "+f"(acc[mi][2 * np + 1][1]),
                          "+f"(acc[mi][2 * np + 1][2]), "+f"(acc[mi][2 * np + 1][3])
                        : "r"(a[mi][0]), "r"(a[mi][1]), "r"(a[mi][2]), "r"(a[mi][3]),
                          "r"(b2), "r"(b3));
                }
            }
        }

        __syncthreads();
        if (kt + 2 < NKT) load_stage(kt + 2, buf);
        else asm volatile("cp.async.commit_group;\n" ::: "memory");
    }

    // ---- epilogue: per-row S1 += exp(logit-1), S2 += p*logit, S3 += p*log(p) ----
    const int rowBase = mt * 128 + wm * 32 + (lane >> 2);
    const int colBase = nt * 128 + wn * 64 + ((lane & 3) << 1);

    #pragma unroll
    for (int mi = 0; mi < 2; ++mi) {
        #pragma unroll
        for (int h = 0; h < 2; ++h) {
            const int r = rowBase + mi * 16 + h * 8;
            const float* Prow = P + (size_t)r * V_SIZE;
            float s1 = 0.f, s2 = 0.f, s3 = 0.f;
            #pragma unroll
            for (int ni = 0; ni < 8; ++ni) {
                #pragma unroll
                for (int e = 0; e < 2; ++e) {
                    int v = colBase + ni * 8 + e;
                    if (v < V_SIZE) {
                        float lg = acc[mi][ni][h * 2 + e];
                        float p  = __ldg(Prow + v);
                        s1 += exp2f(fmaf(lg, LOG2E, -LOG2E));
                        s2 = fmaf(p, lg, s2);
                        s3 = fmaf(p, __logf(fmaxf(p, 1e-12f)), s3);
                    }
                }
            }
            s1 += __shfl_xor_sync(0xffffffffu, s1, 1);
            s1 += __shfl_xor_sync(0xffffffffu, s1, 2);
            s2 += __shfl_xor_sync(0xffffffffu, s2, 1);
            s2 += __shfl_xor_sync(0xffffffffu, s2, 2);
            s3 += __shfl_xor_sync(0xffffffffu, s3, 1);
            s3 += __shfl_xor_sync(0xffffffffu, s3, 2);
            if ((lane & 3) == 0) {
                atomicAdd(&g_S1[r], s1);
                atomicAdd(&g_S2[r], s2);
                atomicAdd(&g_S3[r], s3);
            }
        }
    }
}

// ---------------- finalize: combine per-row stats + radial loss ----------------
__global__ __launch_bounds__(1024) void finalize_kernel(const float* __restrict__ TE,
                                                        float* __restrict__ out) {
    const int t = threadIdx.x;
    float v0 = 0.f, v1 = 0.f, v2 = 0.f, v3 = 0.f, v4 = 0.f;
    for (int r = t; r < MROWS; r += 1024) {
        v0 += g_S3[r] - g_S2[r] + 1.f + __logf(g_S1[r]);   // per-row KL
        float rr = g_rs[r];
        v1 += rr;
        float Hn = fminf(fmaxf(TE[r] * (1.f / LOG_V), 0.f), 1.f);
        float rtg = 3.0f / (1.f + expf(Hn));               // sigmoid(-H) * R_MAX
        float d = rr - rtg;
        v2 = fmaf(d, d, v2);
        v3 += rtg;
        v4 += Hn;
    }
    #pragma unroll
    for (int o = 16; o > 0; o >>= 1) {
        v0 += __shfl_xor_sync(0xffffffffu, v0, o);
        v1 += __shfl_xor_sync(0xffffffffu, v1, o);
        v2 += __shfl_xor_sync(0xffffffffu, v2, o);
        v3 += __shfl_xor_sync(0xffffffffu, v3, o);
        v4 += __shfl_xor_sync(0xffffffffu, v4, o);
    }
    __shared__ float sb[32][5];
    if ((t & 31) == 0) {
        int w = t >> 5;
        sb[w][0] = v0; sb[w][1] = v1; sb[w][2] = v2; sb[w][3] = v3; sb[w][4] = v4;
    }
    __syncthreads();
    if (t < 32) {
        float u0 = sb[t][0], u1 = sb[t][1], u2 = sb[t][2], u3 = sb[t][3], u4 = sb[t][4];
        #pragma unroll
        for (int o = 16; o > 0; o >>= 1) {
            u0 += __shfl_xor_sync(0xffffffffu, u0, o);
            u1 += __shfl_xor_sync(0xffffffffu, u1, o);
            u2 += __shfl_xor_sync(0xffffffffu, u2, o);
            u3 += __shfl_xor_sync(0xffffffffu, u3, o);
            u4 += __shfl_xor_sync(0xffffffffu, u4, o);
        }
        if (t == 0) {
            const float inv = 1.f / (float)MROWS;
            float l_ang = u0 * inv;
            float l_rad = u2 * inv;
            out[0] = l_ang + 0.1f * l_rad;
            out[1] = l_ang;
            out[2] = l_rad;
            out[3] = u1 * inv;   // mean r_s
            out[4] = u3 * inv;   // mean r_target
            out[5] = u4 * inv;   // mean H_norm
        }
    }
}

// ---------------- launch ----------------
extern "C" void kernel_launch(void* const* d_in, const int* in_sizes, int n_in,
                              void* d_out, int out_size) {
    const float* h  = (const float*)d_in[0];   // (2,1024,769)
    const float* W  = (const float*)d_in[1];   // (50257,769)
    const float* P  = (const float*)d_in[2];   // (2,1024,50257)
    const float* TE = (const float*)d_in[3];   // (2,1024)
    float* out = (float*)d_out;

    prep_w_kernel<<<NP, 128>>>(W);
    prep_s_kernel<<<MROWS, 128>>>(h);
    gemm_fused_kernel<<<dim3(MROWS / 128, NP / 128), 256>>>(P);
    finalize_kernel<<<1, 1024>>>(TE, out);
}